// round 4
// baseline (speedup 1.0000x reference)
#include <cuda_runtime.h>

// ROIAlign / crop_and_resize (bilinear, extrapolation_value = 0)
// feature_map: [8, 64, 64, 256] f32 (B,H,W,C), rois: [8,128,4] f32
// out: [1024, 14, 14, 256] f32
//
// One warp per (roi, output row): ROI + y-params hoisted, loop over 14 cols.
// Lane covers channels [lane*4, lane*4+4) and [128 + lane*4, ...): 8 gather
// LDG.128 + 2 streaming STG.128 per pixel.

#define B 8
#define H 64
#define W 64
#define C 256
#define NUM_ROIS 128
#define N_TOTAL (B * NUM_ROIS)       // 1024
#define CROP 14
#define ROW_TASKS (N_TOTAL * CROP)   // 14336
#define WARPS_PER_BLOCK 8

__global__ __launch_bounds__(256) void roialign_kernel(
    const float* __restrict__ fm,
    const float* __restrict__ rois,
    float* __restrict__ out)
{
    const int lane = threadIdx.x & 31;
    const int wid  = threadIdx.x >> 5;
    const int task = blockIdx.x * WARPS_PER_BLOCK + wid;   // (roi, row)

    const int n = task / CROP;          // roi index
    const int i = task - n * CROP;      // output row
    const int b = n >> 7;               // batch

    // ROI coords (warp-broadcast 16B load)
    const float4 r = __ldg((const float4*)(rois + n * 4));
    const float y1 = r.x, x1 = r.y, y2 = r.z, x2 = r.w;

    const float h_scale = (y2 - y1) * (float)(H - 1) / (float)(CROP - 1);
    const float w_scale = (x2 - x1) * (float)(W - 1) / (float)(CROP - 1);

    // ---- y params (hoisted for the whole row) ----
    const float in_y = fmaf((float)i, h_scale, y1 * (float)(H - 1));
    const bool  vy   = (in_y >= 0.f) && (in_y <= (float)(H - 1));
    const float fy   = floorf(in_y);
    const float yl   = in_y - fy;
    const int ty = min(max((int)fy, 0), H - 1);
    const int by = min(max((int)ceilf(in_y), 0), H - 1);

    const size_t base = (size_t)b * (H * W * C);
    const float* rowT = fm + base + (size_t)ty * (W * C) + lane * 4;
    const float* rowB = fm + base + (size_t)by * (W * C) + lane * 4;

    const float x0 = x1 * (float)(W - 1);
    float* op = out + (size_t)(n * (CROP * CROP) + i * CROP) * C + lane * 4;

    const float omyl = 1.f - yl;

    #pragma unroll 2
    for (int j = 0; j < CROP; j++) {
        const float in_x = fmaf((float)j, w_scale, x0);
        const bool  v    = vy && (in_x >= 0.f) && (in_x <= (float)(W - 1));
        const float fx   = floorf(in_x);
        float xl = in_x - fx;
        const int lx = min(max((int)fx, 0), W - 1);
        const int rx = min(max((int)ceilf(in_x), 0), W - 1);

        float wtl = (1.f - xl) * omyl;
        float wtr = xl * omyl;
        float wbl = (1.f - xl) * yl;
        float wbr = xl * yl;
        if (!v) { wtl = wtr = wbl = wbr = 0.f; }

        const float* ptl = rowT + lx * C;
        const float* ptr_ = rowT + rx * C;
        const float* pbl = rowB + lx * C;
        const float* pbr = rowB + rx * C;

        // 8 independent gathers (two 128-channel halves)
        const float4 tl0 = __ldg((const float4*)(ptl));
        const float4 tr0 = __ldg((const float4*)(ptr_));
        const float4 bl0 = __ldg((const float4*)(pbl));
        const float4 br0 = __ldg((const float4*)(pbr));
        const float4 tl1 = __ldg((const float4*)(ptl + 128));
        const float4 tr1 = __ldg((const float4*)(ptr_ + 128));
        const float4 bl1 = __ldg((const float4*)(pbl + 128));
        const float4 br1 = __ldg((const float4*)(pbr + 128));

        float4 o0, o1;
        o0.x = fmaf(tl0.x, wtl, fmaf(tr0.x, wtr, fmaf(bl0.x, wbl, br0.x * wbr)));
        o0.y = fmaf(tl0.y, wtl, fmaf(tr0.y, wtr, fmaf(bl0.y, wbl, br0.y * wbr)));
        o0.z = fmaf(tl0.z, wtl, fmaf(tr0.z, wtr, fmaf(bl0.z, wbl, br0.z * wbr)));
        o0.w = fmaf(tl0.w, wtl, fmaf(tr0.w, wtr, fmaf(bl0.w, wbl, br0.w * wbr)));
        o1.x = fmaf(tl1.x, wtl, fmaf(tr1.x, wtr, fmaf(bl1.x, wbl, br1.x * wbr)));
        o1.y = fmaf(tl1.y, wtl, fmaf(tr1.y, wtr, fmaf(bl1.y, wbl, br1.y * wbr)));
        o1.z = fmaf(tl1.z, wtl, fmaf(tr1.z, wtr, fmaf(bl1.z, wbl, br1.z * wbr)));
        o1.w = fmaf(tl1.w, wtl, fmaf(tr1.w, wtr, fmaf(bl1.w, wbl, br1.w * wbr)));

        __stcs((float4*)op, o0);
        __stcs((float4*)(op + 128), o1);
        op += C;
    }
}

extern "C" void kernel_launch(void* const* d_in, const int* in_sizes, int n_in,
                              void* d_out, int out_size)
{
    const float* fm   = (const float*)d_in[0];
    const float* rois = (const float*)d_in[1];
    float* out = (float*)d_out;

    roialign_kernel<<<ROW_TASKS / WARPS_PER_BLOCK, 256>>>(fm, rois, out);
}